// round 2
// baseline (speedup 1.0000x reference)
#include <cuda_runtime.h>
#include <cstdint>

#define B_  32
#define T_  2048
#define D_  256
#define H_  256
#define G3_ 768

// Scratch (no cudaMalloc allowed): xg buffer [B,T,768] and layer-1 output [B,T,256]
__device__ float g_xg[(size_t)B_ * T_ * G3_];
__device__ float g_h1[(size_t)B_ * T_ * H_];

// ---------------------------------------------------------------------------
// GEMM: out[m,n] = sum_k A[m,k] * W[n,k] + bias[n]
// A: [M=65536, 256] row-major, W: [768, 256] row-major, out: [M, 768]
// Tiles: BM=128, BN=128, BK=16; 256 threads; 8x8 micro-tile per thread.
// ---------------------------------------------------------------------------
__global__ void __launch_bounds__(256)
gemm_xg_kernel(const float* __restrict__ A, const float* __restrict__ W,
               const float* __restrict__ bias, float* __restrict__ out)
{
    __shared__ float As[128][17];
    __shared__ float Ws[128][17];
    const int tid = threadIdx.x;
    const int tx = tid & 15;   // n
    const int ty = tid >> 4;   // m
    const int bm = blockIdx.x * 128;
    const int bn = blockIdx.y * 128;

    float acc[8][8];
    #pragma unroll
    for (int i = 0; i < 8; i++)
        #pragma unroll
        for (int j = 0; j < 8; j++) acc[i][j] = 0.f;

    for (int kb = 0; kb < 256; kb += 16) {
        #pragma unroll
        for (int r = 0; r < 2; r++) {
            int idx = tid + r * 256;           // 512 float4 slots for a 128x16 tile
            int row = idx >> 2;
            int c4  = (idx & 3) * 4;
            float4 v = *(const float4*)&A[(size_t)(bm + row) * 256 + kb + c4];
            As[row][c4 + 0] = v.x; As[row][c4 + 1] = v.y;
            As[row][c4 + 2] = v.z; As[row][c4 + 3] = v.w;
        }
        #pragma unroll
        for (int r = 0; r < 2; r++) {
            int idx = tid + r * 256;
            int row = idx >> 2;
            int c4  = (idx & 3) * 4;
            float4 v = *(const float4*)&W[(size_t)(bn + row) * 256 + kb + c4];
            Ws[row][c4 + 0] = v.x; Ws[row][c4 + 1] = v.y;
            Ws[row][c4 + 2] = v.z; Ws[row][c4 + 3] = v.w;
        }
        __syncthreads();
        #pragma unroll
        for (int kk = 0; kk < 16; kk++) {
            float a[8], bb[8];
            #pragma unroll
            for (int i = 0; i < 8; i++) a[i] = As[ty * 8 + i][kk];
            #pragma unroll
            for (int j = 0; j < 8; j++) bb[j] = Ws[tx * 8 + j][kk];
            #pragma unroll
            for (int i = 0; i < 8; i++)
                #pragma unroll
                for (int j = 0; j < 8; j++)
                    acc[i][j] += a[i] * bb[j];
        }
        __syncthreads();
    }

    const float4 b0 = *(const float4*)&bias[bn + tx * 8];
    const float4 b1 = *(const float4*)&bias[bn + tx * 8 + 4];
    #pragma unroll
    for (int i = 0; i < 8; i++) {
        float4 v0 = make_float4(acc[i][0] + b0.x, acc[i][1] + b0.y,
                                acc[i][2] + b0.z, acc[i][3] + b0.w);
        float4 v1 = make_float4(acc[i][4] + b1.x, acc[i][5] + b1.y,
                                acc[i][6] + b1.z, acc[i][7] + b1.w);
        size_t o = (size_t)(bm + ty * 8 + i) * G3_ + bn + tx * 8;
        *(float4*)&out[o]     = v0;
        *(float4*)&out[o + 4] = v1;
    }
}

// ---------------------------------------------------------------------------
// Recurrent kernel: one cluster of 4 CTAs per batch element (grid = 128 CTAs).
// CTA (rank c) owns hidden chunk j in [c*64, c*64+64) => 192 of the 768 Whh
// rows, held in REGISTERS (4 rows x 32-wide K-slice per thread; 384 threads).
// Per step: reg-resident GEMV vs smem h -> shfl-reduce -> gates -> DSMEM
// broadcast of the 64-value h chunk to all 4 CTAs -> cluster barrier.
// ---------------------------------------------------------------------------
#define RTHREADS 384

__device__ __forceinline__ unsigned smem_u32(const void* p) {
    unsigned a;
    asm("{ .reg .u64 t; cvta.to.shared.u64 t, %1; cvt.u32.u64 %0, t; }"
        : "=r"(a) : "l"(p));
    return a;
}
__device__ __forceinline__ void st_cluster_f32(unsigned addr, unsigned rank, float v) {
    asm volatile(
        "{ .reg .b32 r; mapa.shared::cluster.u32 r, %0, %1; st.shared::cluster.f32 [r], %2; }"
        :: "r"(addr), "r"(rank), "f"(v) : "memory");
}
__device__ __forceinline__ void cluster_barrier() {
    asm volatile("barrier.cluster.arrive.release.aligned;" ::: "memory");
    asm volatile("barrier.cluster.wait.acquire.aligned;"   ::: "memory");
}

// padded h layout: h[k] stored at k + (k>>5)*4 (4-float pad per 32) so the 8
// K-slice float4 reads per warp hit distinct bank groups (conflict-free).
__global__ void __cluster_dims__(4, 1, 1) __launch_bounds__(RTHREADS, 1)
gru_rec_kernel(const float* __restrict__ xg, const float* __restrict__ Whh,
               const float* __restrict__ bhh, float* __restrict__ out)
{
    const int tid = threadIdx.x;
    const int s   = tid & 7;    // K-slice (32 wide)
    const int rg  = tid >> 3;   // row group (4 rows), 0..47
    const int b   = blockIdx.x >> 2;
    const int c   = blockIdx.x & 3;

    __shared__ __align__(16) float hb[2][288];  // padded h, double buffered
    __shared__ float hgc[192];                  // reduced Whh@h for this chunk
    __shared__ float xgs[192];                  // staged xg for this step

    // Load this thread's 4x32 weight block into registers.
    float w[4][32];
    #pragma unroll
    for (int q = 0; q < 4; q++) {
        int lr = rg * 4 + q;           // local row 0..191
        int g  = lr >> 6;              // gate 0..2 (r,z,n)
        int jl = lr & 63;              // hidden index within chunk
        const float4* wp =
            (const float4*)(Whh + (size_t)(g * 256 + c * 64 + jl) * 256 + s * 32);
        #pragma unroll
        for (int k4 = 0; k4 < 8; k4++) {
            float4 v = wp[k4];
            w[q][k4 * 4 + 0] = v.x; w[q][k4 * 4 + 1] = v.y;
            w[q][k4 * 4 + 2] = v.z; w[q][k4 * 4 + 3] = v.w;
        }
    }

    float b_r = 0.f, b_z = 0.f, b_n = 0.f;
    if (tid < 64) {
        b_r = bhh[c * 64 + tid];
        b_z = bhh[256 + c * 64 + tid];
        b_n = bhh[512 + c * 64 + tid];
    }
    for (int i = tid; i < 2 * 288; i += RTHREADS)
        hb[0][i] = 0.f;                      // zero both buffers (h0 = 0)

    const float* xgb = xg + (size_t)b * T_ * G3_;
    const int xoff = (tid >> 6) * 256 + c * 64 + (tid & 63);  // (g, j) for tid<192
    float xgc = (tid < 192) ? xgb[xoff] : 0.f;                // prefetch t=0

    const int jglob = c * 64 + (tid & 63);              // used for tid<64
    const int pidx  = jglob + ((jglob >> 5) << 2);      // padded index (<288)
    const unsigned addr0 = smem_u32(&hb[0][pidx]);
    const unsigned addr1 = smem_u32(&hb[1][pidx]);
    __syncthreads();

    int cur = 0;
    for (int t = 0; t < T_; t++) {
        if (tid < 192) xgs[tid] = xgc;
        float xgn = 0.f;
        if (tid < 192 && t + 1 < T_)
            xgn = xgb[(size_t)(t + 1) * G3_ + xoff];  // prefetch next step

        // 192x256 GEMV chunk: weights in regs, h broadcast from smem
        float acc[4] = {0.f, 0.f, 0.f, 0.f};
        const float4* h4 = (const float4*)hb[cur];
        #pragma unroll
        for (int i = 0; i < 8; i++) {
            float4 hv = h4[s * 9 + i];
            #pragma unroll
            for (int q = 0; q < 4; q++) {
                acc[q] += w[q][i * 4 + 0] * hv.x;
                acc[q] += w[q][i * 4 + 1] * hv.y;
                acc[q] += w[q][i * 4 + 2] * hv.z;
                acc[q] += w[q][i * 4 + 3] * hv.w;
            }
        }
        // reduce across the 8 K-slices (lanes s=0..7 within each row group)
        #pragma unroll
        for (int q = 0; q < 4; q++) {
            acc[q] += __shfl_xor_sync(0xffffffffu, acc[q], 1);
            acc[q] += __shfl_xor_sync(0xffffffffu, acc[q], 2);
            acc[q] += __shfl_xor_sync(0xffffffffu, acc[q], 4);
        }
        if (s == 0) {
            #pragma unroll
            for (int q = 0; q < 4; q++) hgc[rg * 4 + q] = acc[q];
        }
        __syncthreads();

        if (tid < 64) {
            float hr = hgc[tid]       + b_r;
            float hz = hgc[64 + tid]  + b_z;
            float hn = hgc[128 + tid] + b_n;
            float xr = xgs[tid], xz = xgs[64 + tid], xn = xgs[128 + tid];
            float r  = 1.f / (1.f + __expf(-(xr + hr)));
            float z  = 1.f / (1.f + __expf(-(xz + hz)));
            float nn = tanhf(xn + r * hn);
            float hprev = hb[cur][pidx];
            float hnew  = (1.f - z) * nn + z * hprev;
            // broadcast to all 4 CTAs' next-state buffer (incl. self)
            unsigned dsta = cur ? addr0 : addr1;
            #pragma unroll
            for (int p = 0; p < 4; p++) st_cluster_f32(dsta, p, hnew);
            out[((size_t)b * T_ + t) * H_ + jglob] = hnew;
        }

        // cluster barrier: release DSMEM stores / acquire for next-step reads
        cluster_barrier();
        xgc = xgn;
        cur ^= 1;
    }
}

// ---------------------------------------------------------------------------
static void launch_rec(const float* xg, const float* Whh, const float* bhh,
                       float* out)
{
    cudaLaunchConfig_t cfg = {};
    cfg.gridDim  = dim3(B_ * 4, 1, 1);
    cfg.blockDim = dim3(RTHREADS, 1, 1);
    cfg.dynamicSmemBytes = 0;
    cfg.stream = 0;
    cudaLaunchAttribute attrs[1];
    attrs[0].id = cudaLaunchAttributeClusterDimension;
    attrs[0].val.clusterDim.x = 4;
    attrs[0].val.clusterDim.y = 1;
    attrs[0].val.clusterDim.z = 1;
    cfg.attrs = attrs;
    cfg.numAttrs = 1;
    cudaLaunchKernelEx(&cfg, gru_rec_kernel, xg, Whh, bhh, out);
}

extern "C" void kernel_launch(void* const* d_in, const int* in_sizes, int n_in,
                              void* d_out, int out_size)
{
    (void)in_sizes; (void)n_in; (void)out_size;
    const float* x   = (const float*)d_in[0];
    const float* Wih = (const float*)d_in[1];
    const float* Whh = (const float*)d_in[2];
    const float* bih = (const float*)d_in[3];
    const float* bhh = (const float*)d_in[4];
    float* out = (float*)d_out;

    float* xgp; cudaGetSymbolAddress((void**)&xgp, g_xg);
    float* h1p; cudaGetSymbolAddress((void**)&h1p, g_h1);

    const dim3 ggrid(B_ * T_ / 128, G3_ / 128);

    // Layer 0
    gemm_xg_kernel<<<ggrid, 256>>>(x, Wih, bih, xgp);
    launch_rec(xgp, Whh, bhh, h1p);
    // Layer 1
    gemm_xg_kernel<<<ggrid, 256>>>(h1p, Wih + (size_t)G3_ * D_, bih + G3_, xgp);
    launch_rec(xgp, Whh + (size_t)G3_ * H_, bhh + G3_, out);
}

// round 3
// speedup vs baseline: 1.3200x; 1.3200x over previous
#include <cuda_runtime.h>
#include <cstdint>

#define B_  32
#define T_  2048
#define D_  256
#define H_  256
#define G3_ 768

// Scratch (no cudaMalloc allowed): xg buffer [B,T,768] and layer-1 output [B,T,256]
__device__ float g_xg[(size_t)B_ * T_ * G3_];
__device__ float g_h1[(size_t)B_ * T_ * H_];

// ---------------------------------------------------------------------------
// GEMM: out[m,n] = sum_k A[m,k] * W[n,k] + bias[n]   (unchanged from R2, passing)
// ---------------------------------------------------------------------------
__global__ void __launch_bounds__(256)
gemm_xg_kernel(const float* __restrict__ A, const float* __restrict__ W,
               const float* __restrict__ bias, float* __restrict__ out)
{
    __shared__ float As[128][17];
    __shared__ float Ws[128][17];
    const int tid = threadIdx.x;
    const int tx = tid & 15;   // n
    const int ty = tid >> 4;   // m
    const int bm = blockIdx.x * 128;
    const int bn = blockIdx.y * 128;

    float acc[8][8];
    #pragma unroll
    for (int i = 0; i < 8; i++)
        #pragma unroll
        for (int j = 0; j < 8; j++) acc[i][j] = 0.f;

    for (int kb = 0; kb < 256; kb += 16) {
        #pragma unroll
        for (int r = 0; r < 2; r++) {
            int idx = tid + r * 256;
            int row = idx >> 2;
            int c4  = (idx & 3) * 4;
            float4 v = *(const float4*)&A[(size_t)(bm + row) * 256 + kb + c4];
            As[row][c4 + 0] = v.x; As[row][c4 + 1] = v.y;
            As[row][c4 + 2] = v.z; As[row][c4 + 3] = v.w;
        }
        #pragma unroll
        for (int r = 0; r < 2; r++) {
            int idx = tid + r * 256;
            int row = idx >> 2;
            int c4  = (idx & 3) * 4;
            float4 v = *(const float4*)&W[(size_t)(bn + row) * 256 + kb + c4];
            Ws[row][c4 + 0] = v.x; Ws[row][c4 + 1] = v.y;
            Ws[row][c4 + 2] = v.z; Ws[row][c4 + 3] = v.w;
        }
        __syncthreads();
        #pragma unroll
        for (int kk = 0; kk < 16; kk++) {
            float a[8], bb[8];
            #pragma unroll
            for (int i = 0; i < 8; i++) a[i] = As[ty * 8 + i][kk];
            #pragma unroll
            for (int j = 0; j < 8; j++) bb[j] = Ws[tx * 8 + j][kk];
            #pragma unroll
            for (int i = 0; i < 8; i++)
                #pragma unroll
                for (int j = 0; j < 8; j++)
                    acc[i][j] += a[i] * bb[j];
        }
        __syncthreads();
    }

    const float4 b0 = *(const float4*)&bias[bn + tx * 8];
    const float4 b1 = *(const float4*)&bias[bn + tx * 8 + 4];
    #pragma unroll
    for (int i = 0; i < 8; i++) {
        float4 v0 = make_float4(acc[i][0] + b0.x, acc[i][1] + b0.y,
                                acc[i][2] + b0.z, acc[i][3] + b0.w);
        float4 v1 = make_float4(acc[i][4] + b1.x, acc[i][5] + b1.y,
                                acc[i][6] + b1.z, acc[i][7] + b1.w);
        size_t o = (size_t)(bm + ty * 8 + i) * G3_ + bn + tx * 8;
        *(float4*)&out[o]     = v0;
        *(float4*)&out[o + 4] = v1;
    }
}

// ---------------------------------------------------------------------------
// Recurrent kernel: cluster of 4 CTAs per batch element (grid = 128 CTAs).
// CTA rank c owns hidden chunk [c*64, c*64+64) => 192 Whh rows in REGISTERS
// (2 rows x 64-wide K-slice per thread; 384 threads).
// Per step: reg GEMV vs smem h -> 2-level shfl reduce -> gates (fast MUFU) ->
// DSMEM broadcast of 64 h values -> mbarrier handshake (NOT barrier.cluster).
// ---------------------------------------------------------------------------
#define RTHREADS 384
#define HPAD 272   // 256 + 4-float pad per 64

__device__ __forceinline__ unsigned smem_u32(const void* p) {
    unsigned a;
    asm("{ .reg .u64 t; cvta.to.shared.u64 t, %1; cvt.u32.u64 %0, t; }"
        : "=r"(a) : "l"(p));
    return a;
}
__device__ __forceinline__ void st_cluster_f32(unsigned addr, unsigned rank, float v) {
    asm volatile(
        "{ .reg .b32 r; mapa.shared::cluster.u32 r, %0, %1; st.shared::cluster.f32 [r], %2; }"
        :: "r"(addr), "r"(rank), "f"(v) : "memory");
}
__device__ __forceinline__ void mbar_init(unsigned addr, unsigned count) {
    asm volatile("mbarrier.init.shared.b64 [%0], %1;" :: "r"(addr), "r"(count) : "memory");
}
__device__ __forceinline__ void mbar_arrive_peer(unsigned addr, unsigned rank) {
    asm volatile(
        "{ .reg .b32 r; mapa.shared::cluster.u32 r, %0, %1; "
        "mbarrier.arrive.release.cluster.shared::cluster.b64 _, [r]; }"
        :: "r"(addr), "r"(rank) : "memory");
}
__device__ __forceinline__ void mbar_wait_cluster(unsigned addr, unsigned parity) {
    asm volatile(
        "{\n\t.reg .pred P1;\n\t"
        "WAIT_%=:\n\t"
        "mbarrier.try_wait.parity.acquire.cluster.shared::cta.b64 P1, [%0], %1, 0x989680;\n\t"
        "@P1 bra DONE_%=;\n\t"
        "bra WAIT_%=;\n\t"
        "DONE_%=:\n\t}"
        :: "r"(addr), "r"(parity) : "memory");
}
__device__ __forceinline__ void cluster_barrier() {
    asm volatile("barrier.cluster.arrive.aligned;" ::: "memory");
    asm volatile("barrier.cluster.wait.aligned;"   ::: "memory");
}
__device__ __forceinline__ float fast_sigmoid(float x) {
    return 1.f / (1.f + __expf(-x));
}
__device__ __forceinline__ float fast_tanh(float x) {
    // 2*sigmoid(2x) - 1; saturates cleanly (no NaN at +-inf)
    return 2.f / (1.f + __expf(-2.f * x)) - 1.f;
}

// padded h layout: h[k] stored at k + (k>>6)*4 so the 4 K-slice float4 streams
// hit distinct bank groups (broadcast within a slice; conflict-free across).
__global__ void __cluster_dims__(4, 1, 1) __launch_bounds__(RTHREADS, 1)
gru_rec_kernel(const float* __restrict__ xg, const float* __restrict__ Whh,
               const float* __restrict__ bhh, float* __restrict__ out)
{
    const int tid = threadIdx.x;
    const int s   = tid & 3;    // K-slice (64 wide)
    const int rg  = tid >> 2;   // row group (2 rows), 0..95
    const int b   = blockIdx.x >> 2;
    const int c   = blockIdx.x & 3;

    __shared__ __align__(16) float hb[2][HPAD];  // padded h, double buffered
    __shared__ float hgc[192];                   // reduced Whh@h for this chunk
    __shared__ float xgs[192];                   // staged xg for this step
    __shared__ __align__(8) unsigned long long mbar_s[2];

    // Load this thread's 2x64 weight block into registers.
    float w[2][64];
    #pragma unroll
    for (int q = 0; q < 2; q++) {
        int lr = rg * 2 + q;           // local row 0..191
        int g  = lr >> 6;              // gate 0..2 (r,z,n)
        int jl = lr & 63;              // hidden index within chunk
        const float4* wp =
            (const float4*)(Whh + (size_t)(g * 256 + c * 64 + jl) * 256 + s * 64);
        #pragma unroll
        for (int k4 = 0; k4 < 16; k4++) {
            float4 v = wp[k4];
            w[q][k4 * 4 + 0] = v.x; w[q][k4 * 4 + 1] = v.y;
            w[q][k4 * 4 + 2] = v.z; w[q][k4 * 4 + 3] = v.w;
        }
    }

    float b_r = 0.f, b_z = 0.f, b_n = 0.f;
    if (tid < 64) {
        b_r = bhh[c * 64 + tid];
        b_z = bhh[256 + c * 64 + tid];
        b_n = bhh[512 + c * 64 + tid];
    }
    for (int i = tid; i < 2 * HPAD; i += RTHREADS)
        hb[0][i] = 0.f;                      // zero both buffers (h0 = 0)

    const unsigned mb0 = smem_u32(&mbar_s[0]);
    const unsigned mb1 = smem_u32(&mbar_s[1]);
    if (tid == 0) { mbar_init(mb0, 4); mbar_init(mb1, 4); }

    const float* xgb = xg + (size_t)b * T_ * G3_;
    const int xoff = (tid >> 6) * 256 + c * 64 + (tid & 63);  // (g, j) for tid<192
    float xgc = (tid < 192) ? xgb[xoff] : 0.f;                // prefetch t=0

    const int jglob = c * 64 + (tid & 63);              // used for tid<64
    const int pidx  = jglob + ((jglob >> 6) << 2);      // padded index (<HPAD)
    const unsigned addr0 = smem_u32(&hb[0][pidx]);
    const unsigned addr1 = smem_u32(&hb[1][pidx]);
    __syncthreads();
    cluster_barrier();   // all mbarriers initialized before any remote arrive

    int ph0 = 0, ph1 = 0;
    int cur = 0;
    for (int t = 0; t < T_; t++) {
        // (1) wait for this step's h buffer to be fully delivered
        if (t) {
            unsigned wa = cur ? mb1 : mb0;
            int p = cur ? ph1 : ph0;
            mbar_wait_cluster(wa, p);
            if (cur) ph1 ^= 1; else ph0 ^= 1;
        }
        // (2) stage this step's xg; (3) prefetch next step's xg
        if (tid < 192) xgs[tid] = xgc;
        float xgn = 0.f;
        if (tid < 192 && t + 1 < T_)
            xgn = xgb[(size_t)(t + 1) * G3_ + xoff];

        // (4) 192x256 GEMV chunk: weights in regs, h broadcast from smem
        const float* hcur = hb[cur];
        float acc0 = 0.f, acc1 = 0.f;
        const float4* h4 = (const float4*)hcur;
        #pragma unroll
        for (int i = 0; i < 16; i++) {
            float4 hv = h4[s * 17 + i];
            acc0 += w[0][i * 4 + 0] * hv.x; acc0 += w[0][i * 4 + 1] * hv.y;
            acc0 += w[0][i * 4 + 2] * hv.z; acc0 += w[0][i * 4 + 3] * hv.w;
            acc1 += w[1][i * 4 + 0] * hv.x; acc1 += w[1][i * 4 + 1] * hv.y;
            acc1 += w[1][i * 4 + 2] * hv.z; acc1 += w[1][i * 4 + 3] * hv.w;
        }
        // (5) reduce across the 4 K-slices (lanes s=0..3 within each quad)
        acc0 += __shfl_xor_sync(0xffffffffu, acc0, 1);
        acc0 += __shfl_xor_sync(0xffffffffu, acc0, 2);
        acc1 += __shfl_xor_sync(0xffffffffu, acc1, 1);
        acc1 += __shfl_xor_sync(0xffffffffu, acc1, 2);
        if (s == 0) { hgc[rg * 2] = acc0; hgc[rg * 2 + 1] = acc1; }
        __syncthreads();   // (6) hgc + xgs visible to gate warps

        // (7) gates + broadcast (warps 0,1 only)
        if (tid < 64) {
            float hr = hgc[tid]       + b_r;
            float hz = hgc[64 + tid]  + b_z;
            float hn = hgc[128 + tid] + b_n;
            float xr = xgs[tid], xz = xgs[64 + tid], xn = xgs[128 + tid];
            float r  = fast_sigmoid(xr + hr);
            float z  = fast_sigmoid(xz + hz);
            float nn = fast_tanh(xn + r * hn);
            float hprev = hcur[pidx];
            float hnew  = (1.f - z) * nn + z * hprev;
            unsigned dsta = cur ? addr0 : addr1;   // write buffer cur^1
            #pragma unroll
            for (int p = 0; p < 4; p++) st_cluster_f32(dsta, p, hnew);
            out[((size_t)b * T_ + t) * H_ + jglob] = hnew;
            asm volatile("bar.sync 3, 64;" ::: "memory");  // both gate warps' stores done
            if (tid < 4) {
                unsigned am = cur ? mb0 : mb1;     // mbar of buffer cur^1
                mbar_arrive_peer(am, (unsigned)tid);
            }
        }

        xgc = xgn;
        cur ^= 1;
    }
    cluster_barrier();   // don't exit while peers' DSMEM stores are in flight
}

// ---------------------------------------------------------------------------
static void launch_rec(const float* xg, const float* Whh, const float* bhh,
                       float* out)
{
    cudaLaunchConfig_t cfg = {};
    cfg.gridDim  = dim3(B_ * 4, 1, 1);
    cfg.blockDim = dim3(RTHREADS, 1, 1);
    cfg.dynamicSmemBytes = 0;
    cfg.stream = 0;
    cudaLaunchAttribute attrs[1];
    attrs[0].id = cudaLaunchAttributeClusterDimension;
    attrs[0].val.clusterDim.x = 4;
    attrs[0].val.clusterDim.y = 1;
    attrs[0].val.clusterDim.z = 1;
    cfg.attrs = attrs;
    cfg.numAttrs = 1;
    cudaLaunchKernelEx(&cfg, gru_rec_kernel, xg, Whh, bhh, out);
}

extern "C" void kernel_launch(void* const* d_in, const int* in_sizes, int n_in,
                              void* d_out, int out_size)
{
    (void)in_sizes; (void)n_in; (void)out_size;
    const float* x   = (const float*)d_in[0];
    const float* Wih = (const float*)d_in[1];
    const float* Whh = (const float*)d_in[2];
    const float* bih = (const float*)d_in[3];
    const float* bhh = (const float*)d_in[4];
    float* out = (float*)d_out;

    float* xgp; cudaGetSymbolAddress((void**)&xgp, g_xg);
    float* h1p; cudaGetSymbolAddress((void**)&h1p, g_h1);

    const dim3 ggrid(B_ * T_ / 128, G3_ / 128);

    // Layer 0
    gemm_xg_kernel<<<ggrid, 256>>>(x, Wih, bih, xgp);
    launch_rec(xgp, Whh, bhh, h1p);
    // Layer 1
    gemm_xg_kernel<<<ggrid, 256>>>(h1p, Wih + (size_t)G3_ * D_, bih + G3_, xgp);
    launch_rec(xgp, Whh + (size_t)G3_ * H_, bhh + G3_, out);
}

// round 4
// speedup vs baseline: 1.3316x; 1.0088x over previous
#include <cuda_runtime.h>
#include <cstdint>

#define B_  32
#define T_  2048
#define D_  256
#define H_  256
#define G3_ 768

// Scratch (no cudaMalloc allowed): xg buffer [B,T,768] and layer-1 output [B,T,256]
__device__ float g_xg[(size_t)B_ * T_ * G3_];
__device__ float g_h1[(size_t)B_ * T_ * H_];

// ---------------------------------------------------------------------------
// GEMM: out[m,n] = sum_k A[m,k] * W[n,k] + bias[n]   (unchanged, passing)
// ---------------------------------------------------------------------------
__global__ void __launch_bounds__(256)
gemm_xg_kernel(const float* __restrict__ A, const float* __restrict__ W,
               const float* __restrict__ bias, float* __restrict__ out)
{
    __shared__ float As[128][17];
    __shared__ float Ws[128][17];
    const int tid = threadIdx.x;
    const int tx = tid & 15;   // n
    const int ty = tid >> 4;   // m
    const int bm = blockIdx.x * 128;
    const int bn = blockIdx.y * 128;

    float acc[8][8];
    #pragma unroll
    for (int i = 0; i < 8; i++)
        #pragma unroll
        for (int j = 0; j < 8; j++) acc[i][j] = 0.f;

    for (int kb = 0; kb < 256; kb += 16) {
        #pragma unroll
        for (int r = 0; r < 2; r++) {
            int idx = tid + r * 256;
            int row = idx >> 2;
            int c4  = (idx & 3) * 4;
            float4 v = *(const float4*)&A[(size_t)(bm + row) * 256 + kb + c4];
            As[row][c4 + 0] = v.x; As[row][c4 + 1] = v.y;
            As[row][c4 + 2] = v.z; As[row][c4 + 3] = v.w;
        }
        #pragma unroll
        for (int r = 0; r < 2; r++) {
            int idx = tid + r * 256;
            int row = idx >> 2;
            int c4  = (idx & 3) * 4;
            float4 v = *(const float4*)&W[(size_t)(bn + row) * 256 + kb + c4];
            Ws[row][c4 + 0] = v.x; Ws[row][c4 + 1] = v.y;
            Ws[row][c4 + 2] = v.z; Ws[row][c4 + 3] = v.w;
        }
        __syncthreads();
        #pragma unroll
        for (int kk = 0; kk < 16; kk++) {
            float a[8], bb[8];
            #pragma unroll
            for (int i = 0; i < 8; i++) a[i] = As[ty * 8 + i][kk];
            #pragma unroll
            for (int j = 0; j < 8; j++) bb[j] = Ws[tx * 8 + j][kk];
            #pragma unroll
            for (int i = 0; i < 8; i++)
                #pragma unroll
                for (int j = 0; j < 8; j++)
                    acc[i][j] += a[i] * bb[j];
        }
        __syncthreads();
    }

    const float4 b0 = *(const float4*)&bias[bn + tx * 8];
    const float4 b1 = *(const float4*)&bias[bn + tx * 8 + 4];
    #pragma unroll
    for (int i = 0; i < 8; i++) {
        float4 v0 = make_float4(acc[i][0] + b0.x, acc[i][1] + b0.y,
                                acc[i][2] + b0.z, acc[i][3] + b0.w);
        float4 v1 = make_float4(acc[i][4] + b1.x, acc[i][5] + b1.y,
                                acc[i][6] + b1.z, acc[i][7] + b1.w);
        size_t o = (size_t)(bm + ty * 8 + i) * G3_ + bn + tx * 8;
        *(float4*)&out[o]     = v0;
        *(float4*)&out[o + 4] = v1;
    }
}

// ---------------------------------------------------------------------------
// Recurrent kernel: cluster of 4 CTAs per batch element (grid = 128 CTAs).
// CTA rank c owns hidden chunk [c*64, c*64+64) => 192 Whh rows in REGISTERS,
// now as PACKED f32x2 K-pairs (2 rows x 32 pairs per thread; 384 threads).
// GEMV uses fma.rn.f32x2 (SASS FFMA2): 2 MACs/instr -> issue floor halved.
// ---------------------------------------------------------------------------
#define RTHREADS 384
#define HPAD 272   // 256 + 4-float pad per 64

typedef unsigned long long u64t;

__device__ __forceinline__ unsigned smem_u32(const void* p) {
    unsigned a;
    asm("{ .reg .u64 t; cvta.to.shared.u64 t, %1; cvt.u32.u64 %0, t; }"
        : "=r"(a) : "l"(p));
    return a;
}
__device__ __forceinline__ void st_cluster_f32(unsigned addr, unsigned rank, float v) {
    asm volatile(
        "{ .reg .b32 r; mapa.shared::cluster.u32 r, %0, %1; st.shared::cluster.f32 [r], %2; }"
        :: "r"(addr), "r"(rank), "f"(v) : "memory");
}
__device__ __forceinline__ void mbar_init(unsigned addr, unsigned count) {
    asm volatile("mbarrier.init.shared.b64 [%0], %1;" :: "r"(addr), "r"(count) : "memory");
}
__device__ __forceinline__ void mbar_arrive_peer(unsigned addr, unsigned rank) {
    asm volatile(
        "{ .reg .b32 r; mapa.shared::cluster.u32 r, %0, %1; "
        "mbarrier.arrive.release.cluster.shared::cluster.b64 _, [r]; }"
        :: "r"(addr), "r"(rank) : "memory");
}
__device__ __forceinline__ void mbar_wait_cluster(unsigned addr, unsigned parity) {
    asm volatile(
        "{\n\t.reg .pred P1;\n\t"
        "WAIT_%=:\n\t"
        "mbarrier.try_wait.parity.acquire.cluster.shared::cta.b64 P1, [%0], %1, 0x989680;\n\t"
        "@P1 bra DONE_%=;\n\t"
        "bra WAIT_%=;\n\t"
        "DONE_%=:\n\t}"
        :: "r"(addr), "r"(parity) : "memory");
}
__device__ __forceinline__ void cluster_barrier() {
    asm volatile("barrier.cluster.arrive.aligned;" ::: "memory");
    asm volatile("barrier.cluster.wait.aligned;"   ::: "memory");
}
__device__ __forceinline__ u64t ffma2(u64t a, u64t b, u64t c) {
    u64t d;
    asm("fma.rn.f32x2 %0, %1, %2, %3;" : "=l"(d) : "l"(a), "l"(b), "l"(c));
    return d;
}
__device__ __forceinline__ u64t add2(u64t a, u64t b) {
    u64t d;
    asm("add.rn.f32x2 %0, %1, %2;" : "=l"(d) : "l"(a), "l"(b));
    return d;
}
__device__ __forceinline__ float hsum2(u64t v) {
    float lo, hi;
    asm("mov.b64 {%0, %1}, %2;" : "=f"(lo), "=f"(hi) : "l"(v));
    return lo + hi;
}
__device__ __forceinline__ float fast_sigmoid(float x) {
    return 1.f / (1.f + __expf(-x));
}
__device__ __forceinline__ float fast_tanh(float x) {
    return 2.f / (1.f + __expf(-2.f * x)) - 1.f;   // saturates cleanly
}

// padded h layout: h[k] stored at k + (k>>6)*4; K-slice streams (s=0..3) are
// 272B apart -> distinct bank groups, conflict-free LDS.128 broadcasts.
__global__ void __cluster_dims__(4, 1, 1) __launch_bounds__(RTHREADS, 1)
gru_rec_kernel(const float* __restrict__ xg, const float* __restrict__ Whh,
               const float* __restrict__ bhh, float* __restrict__ out)
{
    const int tid = threadIdx.x;
    const int s   = tid & 3;    // K-slice (64 wide)
    const int rg  = tid >> 2;   // row group (2 rows), 0..95
    const int b   = blockIdx.x >> 2;
    const int c   = blockIdx.x & 3;

    __shared__ __align__(16) float hb[2][HPAD];  // padded h, double buffered
    __shared__ float hgc[192];                   // reduced Whh@h for this chunk
    __shared__ float xgs[192];                   // staged xg for this step
    __shared__ __align__(8) unsigned long long mbar_s[2];

    // Load this thread's 2 rows x 64 K weights as 32 packed f32x2 pairs each.
    u64t w2[2][32];
    #pragma unroll
    for (int q = 0; q < 2; q++) {
        int lr = rg * 2 + q;           // local row 0..191
        int g  = lr >> 6;              // gate 0..2 (r,z,n)
        int jl = lr & 63;              // hidden index within chunk
        const ulonglong2* wp =
            (const ulonglong2*)(Whh + (size_t)(g * 256 + c * 64 + jl) * 256 + s * 64);
        #pragma unroll
        for (int k = 0; k < 16; k++) {
            ulonglong2 v = wp[k];
            w2[q][2 * k]     = v.x;
            w2[q][2 * k + 1] = v.y;
        }
    }

    float b_r = 0.f, b_z = 0.f, b_n = 0.f;
    if (tid < 64) {
        b_r = bhh[c * 64 + tid];
        b_z = bhh[256 + c * 64 + tid];
        b_n = bhh[512 + c * 64 + tid];
    }
    for (int i = tid; i < 2 * HPAD; i += RTHREADS)
        hb[0][i] = 0.f;                      // zero both buffers (h0 = 0)

    const unsigned mb0 = smem_u32(&mbar_s[0]);
    const unsigned mb1 = smem_u32(&mbar_s[1]);
    if (tid == 0) { mbar_init(mb0, 4); mbar_init(mb1, 4); }

    const float* xgb = xg + (size_t)b * T_ * G3_;
    const int xoff = (tid >> 6) * 256 + c * 64 + (tid & 63);  // (g, j) for tid<192
    float xgc = (tid < 192) ? xgb[xoff] : 0.f;                // prefetch t=0

    const int jglob = c * 64 + (tid & 63);              // used for tid<64
    const int pidx  = jglob + ((jglob >> 6) << 2);      // padded index (<HPAD)
    const unsigned addr0 = smem_u32(&hb[0][pidx]);
    const unsigned addr1 = smem_u32(&hb[1][pidx]);
    float hreg = 0.f;                                   // this thread's h (tid<64)
    __syncthreads();
    cluster_barrier();   // all mbarriers initialized before any remote arrive

    int ph0 = 0, ph1 = 0;
    int cur = 0;
    for (int t = 0; t < T_; t++) {
        // (1) wait for this step's h buffer to be fully delivered
        if (t) {
            unsigned wa = cur ? mb1 : mb0;
            int p = cur ? ph1 : ph0;
            mbar_wait_cluster(wa, p);
            if (cur) ph1 ^= 1; else ph0 ^= 1;
        }
        // (2) stage this step's xg; (3) prefetch next step's xg
        if (tid < 192) xgs[tid] = xgc;
        float xgn = 0.f;
        if (tid < 192 && t + 1 < T_)
            xgn = xgb[(size_t)(t + 1) * G3_ + xoff];

        // (4) 192x256 GEMV chunk via packed FFMA2: 16 LDS.128 + 64 fma.f32x2
        const ulonglong2* h2 = (const ulonglong2*)hb[cur];
        u64t a00 = 0, a01 = 0, a10 = 0, a11 = 0;
        #pragma unroll
        for (int i = 0; i < 16; i++) {
            ulonglong2 hv = h2[s * 17 + i];
            a00 = ffma2(w2[0][2 * i],     hv.x, a00);
            a01 = ffma2(w2[0][2 * i + 1], hv.y, a01);
            a10 = ffma2(w2[1][2 * i],     hv.x, a10);
            a11 = ffma2(w2[1][2 * i + 1], hv.y, a11);
        }
        float acc0 = hsum2(add2(a00, a01));
        float acc1 = hsum2(add2(a10, a11));
        // (5) reduce across the 4 K-slices (lanes s=0..3 within each quad)
        acc0 += __shfl_xor_sync(0xffffffffu, acc0, 1);
        acc0 += __shfl_xor_sync(0xffffffffu, acc0, 2);
        acc1 += __shfl_xor_sync(0xffffffffu, acc1, 1);
        acc1 += __shfl_xor_sync(0xffffffffu, acc1, 2);
        if (s == 0) { hgc[rg * 2] = acc0; hgc[rg * 2 + 1] = acc1; }
        __syncthreads();   // (6) hgc + xgs visible to gate warps

        // (7) gates + broadcast (warps 0,1 only)
        if (tid < 64) {
            float hr = hgc[tid]       + b_r;
            float hz = hgc[64 + tid]  + b_z;
            float hn = hgc[128 + tid] + b_n;
            float xr = xgs[tid], xz = xgs[64 + tid], xn = xgs[128 + tid];
            float r  = fast_sigmoid(xr + hr);
            float z  = fast_sigmoid(xz + hz);
            float nn = fast_tanh(xn + r * hn);
            float hnew = (1.f - z) * nn + z * hreg;   // hreg = own h from last step
            hreg = hnew;
            unsigned dsta = cur ? addr0 : addr1;      // write buffer cur^1
            #pragma unroll
            for (int p = 0; p < 4; p++) st_cluster_f32(dsta, p, hnew);
            out[((size_t)b * T_ + t) * H_ + jglob] = hnew;
            asm volatile("bar.sync 3, 64;" ::: "memory");  // both gate warps' stores done
            if (tid < 4) {
                unsigned am = cur ? mb0 : mb1;        // mbar of buffer cur^1
                mbar_arrive_peer(am, (unsigned)tid);
            }
        }

        xgc = xgn;
        cur ^= 1;
    }
    cluster_barrier();   // don't exit while peers' DSMEM stores are in flight
}

// ---------------------------------------------------------------------------
static void launch_rec(const float* xg, const float* Whh, const float* bhh,
                       float* out)
{
    cudaLaunchConfig_t cfg = {};
    cfg.gridDim  = dim3(B_ * 4, 1, 1);
    cfg.blockDim = dim3(RTHREADS, 1, 1);
    cfg.dynamicSmemBytes = 0;
    cfg.stream = 0;
    cudaLaunchAttribute attrs[1];
    attrs[0].id = cudaLaunchAttributeClusterDimension;
    attrs[0].val.clusterDim.x = 4;
    attrs[0].val.clusterDim.y = 1;
    attrs[0].val.clusterDim.z = 1;
    cfg.attrs = attrs;
    cfg.numAttrs = 1;
    cudaLaunchKernelEx(&cfg, gru_rec_kernel, xg, Whh, bhh, out);
}

extern "C" void kernel_launch(void* const* d_in, const int* in_sizes, int n_in,
                              void* d_out, int out_size)
{
    (void)in_sizes; (void)n_in; (void)out_size;
    const float* x   = (const float*)d_in[0];
    const float* Wih = (const float*)d_in[1];
    const float* Whh = (const float*)d_in[2];
    const float* bih = (const float*)d_in[3];
    const float* bhh = (const float*)d_in[4];
    float* out = (float*)d_out;

    float* xgp; cudaGetSymbolAddress((void**)&xgp, g_xg);
    float* h1p; cudaGetSymbolAddress((void**)&h1p, g_h1);

    const dim3 ggrid(B_ * T_ / 128, G3_ / 128);

    // Layer 0
    gemm_xg_kernel<<<ggrid, 256>>>(x, Wih, bih, xgp);
    launch_rec(xgp, Whh, bhh, h1p);
    // Layer 1
    gemm_xg_kernel<<<ggrid, 256>>>(h1p, Wih + (size_t)G3_ * D_, bih + G3_, xgp);
    launch_rec(xgp, Whh + (size_t)G3_ * H_, bhh + G3_, out);
}